// round 15
// baseline (speedup 1.0000x reference)
#include <cuda_runtime.h>
#include <cuda_bf16.h>
#include <cstddef>
#include <cstdint>

// Problem constants
#define Bn  4
#define Ln  1024
#define En  256
#define Hn  8
#define DHn 32
#define KP2 36   // smem row stride in uint2 (hi,lo) elements; conflict-free LDS.64

// ---------------- scratch (device globals; no allocation allowed) -----------
__device__ float g_q[Bn * Ln * En];        // Q pre-scaled by 1/16, [b][n][h*32+d]
__device__ float g_k[Bn * Hn * Ln * DHn];  // K head-major [b][h][m][d]
__device__ float g_v[Bn * Hn * Ln * DHn];  // V head-major [b][h][m][d]
__device__ float g_attn[Bn * Ln * En];     // attention output [b][n][h*32+d]
__device__ int   g_adj_is_byte;            // 1 = adjacency stored as 1-byte elems

// ---------------- adjacency dtype detection (parallel) -----------------------
__global__ void __launch_bounds__(1024)
detect_adj_kernel(const unsigned char* __restrict__ adj)
{
    __shared__ int ok;
    if (threadIdx.x == 0) ok = 1;
    __syncthreads();
    if (adj[(size_t)threadIdx.x * Ln + threadIdx.x] != 1) ok = 0;  // benign race
    __syncthreads();
    if (threadIdx.x == 0) g_adj_is_byte = ok;
}

// ---------------- tf32 helpers ------------------------------------------------
__device__ __forceinline__ uint32_t cvt_tf32(float x) {
    uint32_t r;
    asm("cvt.rna.tf32.f32 %0, %1;" : "=r"(r) : "f"(x));
    return r;
}

// store 4 consecutive k-elements as interleaved (hi,lo) uint2 pairs
__device__ __forceinline__ void sts_split2(uint2* U, int off, float4 v) {
    uint32_t h0 = cvt_tf32(v.x), h1 = cvt_tf32(v.y);
    uint32_t h2 = cvt_tf32(v.z), h3 = cvt_tf32(v.w);
    uint32_t l0 = cvt_tf32(v.x - __uint_as_float(h0));
    uint32_t l1 = cvt_tf32(v.y - __uint_as_float(h1));
    uint32_t l2 = cvt_tf32(v.z - __uint_as_float(h2));
    uint32_t l3 = cvt_tf32(v.w - __uint_as_float(h3));
    *(uint4*)(U + off)     = make_uint4(h0, l0, h1, l1);
    *(uint4*)(U + off + 2) = make_uint4(h2, l2, h3, l3);
}

__device__ __forceinline__ void mma8(float (&c)[4],
                                     uint32_t a0, uint32_t a1, uint32_t a2, uint32_t a3,
                                     uint32_t b0, uint32_t b1) {
    asm volatile(
        "mma.sync.aligned.m16n8k8.row.col.f32.tf32.tf32.f32 "
        "{%0,%1,%2,%3}, {%4,%5,%6,%7}, {%8,%9}, {%0,%1,%2,%3};"
        : "+f"(c[0]), "+f"(c[1]), "+f"(c[2]), "+f"(c[3])
        : "r"(a0), "r"(a1), "r"(a2), "r"(a3), "r"(b0), "r"(b1));
}

// ---------------- 64x64 tensor-core GEMM body (3xTF32, uint2 hi/lo) ----------
// c[j][0..3] = C tile for warp: rows wr0+g / wr0+g+8, cols wc0+j*8+2t / +1.
// A[4096x256] row-major, W[256x256] row-major (C = A @ W^T), K = 256.
__device__ __forceinline__ void mma64_body(const float* __restrict__ A,
                                           const float* __restrict__ W,
                                           int row0, int col0,
                                           float (&c)[4][4],
                                           uint2* Ua, uint2* Ub)
{
    const int tid  = threadIdx.x;
    const int warp = tid >> 5, lane = tid & 31;
    const int g = lane >> 2, t = lane & 3;
    const int wr0 = (warp & 3) * 16;   // warp row within CTA tile
    const int wc0 = (warp >> 2) * 32;  // warp col within CTA tile

    // loader coords: 4 threads per row, each loads 2 float4 (8 k-floats)
    const int lrow = tid >> 2;
    const int kq   = (tid & 3) * 8;
    const int soff = lrow * KP2 + kq;

    const float* Ap = A + (size_t)(row0 + lrow) * 256 + kq;
    const float* Wp = W + (size_t)(col0 + lrow) * 256 + kq;

    // hoisted fragment row bases (uint2 units)
    const int arow0 = (wr0 + g) * KP2 + t;
    const int arow1 = (wr0 + g + 8) * KP2 + t;
    const int brow  = (wc0 + g) * KP2 + t;

    // prefetch chunk 0
    float4 ra0 = *(const float4*)(Ap);
    float4 ra1 = *(const float4*)(Ap + 4);
    float4 rw0 = *(const float4*)(Wp);
    float4 rw1 = *(const float4*)(Wp + 4);

#pragma unroll 1
    for (int kc = 0; kc < 8; kc++) {        // 8 chunks of K=32
        __syncthreads();                    // prior chunk's frag reads done
        sts_split2(Ua, soff,     ra0);
        sts_split2(Ua, soff + 4, ra1);
        sts_split2(Ub, soff,     rw0);
        sts_split2(Ub, soff + 4, rw1);
        __syncthreads();

        if (kc < 7) {                       // issue next chunk's loads early
            ra0 = *(const float4*)(Ap + (kc + 1) * 32);
            ra1 = *(const float4*)(Ap + (kc + 1) * 32 + 4);
            rw0 = *(const float4*)(Wp + (kc + 1) * 32);
            rw1 = *(const float4*)(Wp + (kc + 1) * 32 + 4);
        }

#pragma unroll
        for (int ks = 0; ks < 4; ks++) {    // 4 k8-steps per chunk
            const int k0 = ks * 8;
            // A fragments: one LDS.64 each fetches (hi,lo)
            const uint2 a0 = Ua[arow0 + k0];
            const uint2 a1 = Ua[arow1 + k0];
            const uint2 a2 = Ua[arow0 + k0 + 4];
            const uint2 a3 = Ua[arow1 + k0 + 4];
#pragma unroll
            for (int j = 0; j < 4; j++) {   // 4 n-tiles of 8 cols
                const uint2 b0 = Ub[brow + j * 8 * KP2 + k0];
                const uint2 b1 = Ub[brow + j * 8 * KP2 + k0 + 4];
                mma8(c[j], a0.x, a1.x, a2.x, a3.x, b0.x, b1.x);  // hi*hi
                mma8(c[j], a0.x, a1.x, a2.x, a3.x, b0.y, b1.y);  // hi*lo
                mma8(c[j], a0.y, a1.y, a2.y, a3.y, b0.x, b1.x);  // lo*hi
            }
        }
    }
}

// ---------------- fused QKV projection (tensor core) --------------------------
__global__ void __launch_bounds__(256)
qkv_gemm_kernel(const float* __restrict__ A,
                const float* __restrict__ Wq, const float* __restrict__ bq,
                const float* __restrict__ Wk, const float* __restrict__ bk,
                const float* __restrict__ Wv, const float* __restrict__ bv)
{
    __shared__ __align__(16) uint2 Ua[64 * KP2];
    __shared__ __align__(16) uint2 Ub[64 * KP2];

    const int wsel = blockIdx.x >> 2;            // 0=Q 1=K 2=V
    const int col0 = (blockIdx.x & 3) * 64;
    const int row0 = blockIdx.y * 64;

    const float* W    = (wsel == 0) ? Wq : (wsel == 1) ? Wk : Wv;
    const float* bias = (wsel == 0) ? bq : (wsel == 1) ? bk : bv;

    float c[4][4];
#pragma unroll
    for (int j = 0; j < 4; j++)
#pragma unroll
        for (int i = 0; i < 4; i++) c[j][i] = 0.f;

    mma64_body(A, W, row0, col0, c, Ua, Ub);

    const int lane = threadIdx.x & 31, warp = threadIdx.x >> 5;
    const int g = lane >> 2, t = lane & 3;
    const int wr0 = (warp & 3) * 16, wc0 = (warp >> 2) * 32;

#pragma unroll
    for (int j = 0; j < 4; j++) {
        const int cc = col0 + wc0 + j * 8 + 2 * t;
        const float b0 = bias[cc], b1 = bias[cc + 1];
#pragma unroll
        for (int half = 0; half < 2; half++) {
            const int r = row0 + wr0 + g + half * 8;
            float v0 = c[j][half * 2 + 0] + b0;
            float v1 = c[j][half * 2 + 1] + b1;
            if (wsel == 0) {
                *(float2*)&g_q[(size_t)r * 256 + cc] =
                    make_float2(v0 * 0.0625f, v1 * 0.0625f);
            } else {
                // r = b*1024 + l ; cc = h*32 + d  ->  [b][h][l][d] (d,d+1 adjacent)
                int idx = (((r >> 10) * Hn + (cc >> 5)) * Ln + (r & 1023)) * DHn + (cc & 31);
                float* dst = (wsel == 1) ? g_k : g_v;
                *(float2*)&dst[idx] = make_float2(v0, v1);
            }
        }
    }
}

// ---------------- output projection (tensor core) -----------------------------
__global__ void __launch_bounds__(256)
out_gemm_kernel(const float* __restrict__ A, const float* __restrict__ W,
                const float* __restrict__ bias, float* __restrict__ C)
{
    __shared__ __align__(16) uint2 Ua[64 * KP2];
    __shared__ __align__(16) uint2 Ub[64 * KP2];

    const int col0 = blockIdx.x * 64;
    const int row0 = blockIdx.y * 64;

    float c[4][4];
#pragma unroll
    for (int j = 0; j < 4; j++)
#pragma unroll
        for (int i = 0; i < 4; i++) c[j][i] = 0.f;

    mma64_body(A, W, row0, col0, c, Ua, Ub);

    const int lane = threadIdx.x & 31, warp = threadIdx.x >> 5;
    const int g = lane >> 2, t = lane & 3;
    const int wr0 = (warp & 3) * 16, wc0 = (warp >> 2) * 32;

#pragma unroll
    for (int j = 0; j < 4; j++) {
        const int cc = col0 + wc0 + j * 8 + 2 * t;
        const float b0 = bias[cc], b1 = bias[cc + 1];
#pragma unroll
        for (int half = 0; half < 2; half++) {
            const int r = row0 + wr0 + g + half * 8;
            *(float2*)&C[(size_t)r * 256 + cc] =
                make_float2(c[j][half * 2 + 0] + b0, c[j][half * 2 + 1] + b1);
        }
    }
}

// ---------------- fused sparse attention (R12/R14 version — known good) ------
__global__ void __launch_bounds__(256)
attn_kernel(const void* __restrict__ AdjRaw, const float* __restrict__ Eg,
            float* __restrict__ Ob)
{
    __shared__ float q_s[En];
    __shared__ int   m_list[Ln];
    __shared__ float sc[Hn][Ln];
    __shared__ int   m_cnt;

    const int n    = blockIdx.x;
    const int b    = blockIdx.y;
    const int tid  = threadIdx.x;
    const int w    = tid >> 5;
    const int lane = tid & 31;
    const int g    = lane >> 3;
    const int sub  = lane & 7;
    const int isbyte = g_adj_is_byte;

    q_s[tid] = g_q[(size_t)(b * Ln + n) * En + tid];
    if (tid == 0) m_cnt = 0;
    __syncthreads();

    const unsigned char* arow8  = (const unsigned char*)AdjRaw + (size_t)(b * Ln + n) * Ln;
    const unsigned int*  arow32 = (const unsigned int*) AdjRaw + (size_t)(b * Ln + n) * Ln;
#pragma unroll
    for (int base = 0; base < Ln; base += 256) {
        int m = base + tid;
        bool valid = isbyte ? (arow8[m] != 0) : (arow32[m] != 0u);
        unsigned bal = __ballot_sync(0xffffffffu, valid);
        int pos = 0;
        if (lane == 0 && bal) pos = atomicAdd(&m_cnt, __popc(bal));
        pos = __shfl_sync(0xffffffffu, pos, 0);
        if (valid) m_list[pos + __popc(bal & ((1u << lane) - 1))] = m;
    }
    __syncthreads();
    const int cnt = m_cnt;

    const float* Kh   = g_k + (size_t)(b * Hn + w) * Ln * DHn;
    const float* Vh   = g_v + (size_t)(b * Hn + w) * Ln * DHn;
    const float* Erow = Eg + (size_t)(b * Ln + n) * Ln * DHn;

    const float4 q4 = *(const float4*)&q_s[w * DHn + sub * 4];

    for (int i = 0; i < cnt; i += 8) {
        const int j0 = i + g, j1 = i + 4 + g;
        const int m0 = m_list[(j0 < cnt) ? j0 : 0];
        const int m1 = m_list[(j1 < cnt) ? j1 : 0];
        const float4 k0 = *(const float4*)(Kh   + (size_t)m0 * DHn + sub * 4);
        const float4 e0 = *(const float4*)(Erow + (size_t)m0 * DHn + sub * 4);
        const float4 k1 = *(const float4*)(Kh   + (size_t)m1 * DHn + sub * 4);
        const float4 e1 = *(const float4*)(Erow + (size_t)m1 * DHn + sub * 4);
        float s0, s1;
        s0 = q4.x * (k0.x + e0.x);
        s1 = q4.x * (k1.x + e1.x);
        s0 = fmaf(q4.y, k0.y + e0.y, s0);
        s1 = fmaf(q4.y, k1.y + e1.y, s1);
        s0 = fmaf(q4.z, k0.z + e0.z, s0);
        s1 = fmaf(q4.z, k1.z + e1.z, s1);
        s0 = fmaf(q4.w, k0.w + e0.w, s0);
        s1 = fmaf(q4.w, k1.w + e1.w, s1);
        s0 += __shfl_xor_sync(0xffffffffu, s0, 1);
        s1 += __shfl_xor_sync(0xffffffffu, s1, 1);
        s0 += __shfl_xor_sync(0xffffffffu, s0, 2);
        s1 += __shfl_xor_sync(0xffffffffu, s1, 2);
        s0 += __shfl_xor_sync(0xffffffffu, s0, 4);
        s1 += __shfl_xor_sync(0xffffffffu, s1, 4);
        if (sub == 0) {
            if (j0 < cnt) sc[w][j0] = s0;
            if (j1 < cnt) sc[w][j1] = s1;
        }
    }
    __syncwarp();

    float mx = -1e30f;
    for (int j = lane; j < cnt; j += 32) mx = fmaxf(mx, sc[w][j]);
#pragma unroll
    for (int off = 16; off > 0; off >>= 1)
        mx = fmaxf(mx, __shfl_xor_sync(0xffffffffu, mx, off));

    float sum = 0.f;
    for (int j = lane; j < cnt; j += 32) {
        float p = __expf(sc[w][j] - mx);
        sc[w][j] = p;
        sum += p;
    }
#pragma unroll
    for (int off = 16; off > 0; off >>= 1)
        sum += __shfl_xor_sync(0xffffffffu, sum, off);
    const float inv = 1.f / sum;
    __syncwarp();

    float4 acc0 = make_float4(0.f, 0.f, 0.f, 0.f);
    float4 acc1 = make_float4(0.f, 0.f, 0.f, 0.f);
    for (int j = 0; j < cnt; j += 8) {
        const int j0 = j + g, j1 = j + 4 + g;
        const bool ok0 = (j0 < cnt), ok1 = (j1 < cnt);
        const int m0 = m_list[ok0 ? j0 : 0];
        const int m1 = m_list[ok1 ? j1 : 0];
        const float p0 = ok0 ? sc[w][j0] : 0.f;
        const float p1 = ok1 ? sc[w][j1] : 0.f;
        const float4 v0 = *(const float4*)(Vh + (size_t)m0 * DHn + sub * 4);
        const float4 v1 = *(const float4*)(Vh + (size_t)m1 * DHn + sub * 4);
        acc0.x = fmaf(p0, v0.x, acc0.x);
        acc0.y = fmaf(p0, v0.y, acc0.y);
        acc0.z = fmaf(p0, v0.z, acc0.z);
        acc0.w = fmaf(p0, v0.w, acc0.w);
        acc1.x = fmaf(p1, v1.x, acc1.x);
        acc1.y = fmaf(p1, v1.y, acc1.y);
        acc1.z = fmaf(p1, v1.z, acc1.z);
        acc1.w = fmaf(p1, v1.w, acc1.w);
    }
    float4 acc = make_float4(acc0.x + acc1.x, acc0.y + acc1.y,
                             acc0.z + acc1.z, acc0.w + acc1.w);
#pragma unroll
    for (int off = 8; off <= 16; off <<= 1) {
        acc.x += __shfl_xor_sync(0xffffffffu, acc.x, off);
        acc.y += __shfl_xor_sync(0xffffffffu, acc.y, off);
        acc.z += __shfl_xor_sync(0xffffffffu, acc.z, off);
        acc.w += __shfl_xor_sync(0xffffffffu, acc.w, off);
    }
    if (g == 0) {
        float4 o = make_float4(acc.x * inv, acc.y * inv, acc.z * inv, acc.w * inv);
        *(float4*)(Ob + (size_t)(b * Ln + n) * En + w * DHn + sub * 4) = o;
    }
}

// ---------------- launch ----------------------------------------------------
extern "C" void kernel_launch(void* const* d_in, const int* in_sizes, int n_in,
                              void* d_out, int out_size)
{
    const float* nf  = (const float*)d_in[0];
    const void*  adj = d_in[1];
    const float* eg  = (const float*)d_in[2];
    const float* Wq = (const float*)d_in[3];
    const float* bq = (const float*)d_in[4];
    const float* Wk = (const float*)d_in[5];
    const float* bk = (const float*)d_in[6];
    const float* Wv = (const float*)d_in[7];
    const float* bv = (const float*)d_in[8];
    const float* Wo = (const float*)d_in[9];
    const float* bo = (const float*)d_in[10];
    float* out = (float*)d_out;

    float *at;
    cudaGetSymbolAddress((void**)&at, g_attn);

    detect_adj_kernel<<<1, 1024>>>((const unsigned char*)adj);

    dim3 qkv_grid(12, (Bn * Ln) / 64);   // 768 CTAs
    qkv_gemm_kernel<<<qkv_grid, 256>>>(nf, Wq, bq, Wk, bk, Wv, bv);

    dim3 agrid(Ln, Bn);                  // 4096 CTAs
    attn_kernel<<<agrid, 256>>>(adj, eg, at);

    dim3 ogrid(En / 64, (Bn * Ln) / 64); // 256 CTAs
    out_gemm_kernel<<<ogrid, 256>>>(at, Wo, bo, out);
}

// round 16
// speedup vs baseline: 1.0783x; 1.0783x over previous
#include <cuda_runtime.h>
#include <cuda_bf16.h>
#include <cstddef>
#include <cstdint>

// Problem constants
#define Bn  4
#define Ln  1024
#define En  256
#define Hn  8
#define DHn 32
#define KPAD 36   // smem k-row stride (floats): conflict-free frag loads, 16B-aligned

// ---------------- scratch (device globals; no allocation allowed) -----------
__device__ float g_q[Bn * Ln * En];        // Q pre-scaled by 1/16, [b][n][h*32+d]
__device__ float g_k[Bn * Hn * Ln * DHn];  // K head-major [b][h][m][d]
__device__ float g_v[Bn * Hn * Ln * DHn];  // V head-major [b][h][m][d]
__device__ float g_attn[Bn * Ln * En];     // attention output [b][n][h*32+d]
__device__ int   g_adj_is_byte;            // 1 = adjacency stored as 1-byte elems

// ---------------- adjacency dtype detection (parallel) -----------------------
__global__ void __launch_bounds__(1024)
detect_adj_kernel(const unsigned char* __restrict__ adj)
{
    __shared__ int ok;
    if (threadIdx.x == 0) ok = 1;
    __syncthreads();
    if (adj[(size_t)threadIdx.x * Ln + threadIdx.x] != 1) ok = 0;  // benign race
    __syncthreads();
    if (threadIdx.x == 0) g_adj_is_byte = ok;
}

// ---------------- bias init (split-K GEMMs accumulate on top) -----------------
// r = blockIdx.x (0..4095), c = threadIdx.x (0..255)
__global__ void __launch_bounds__(256)
bias_init_kernel(const float* __restrict__ bq, const float* __restrict__ bk,
                 const float* __restrict__ bv, const float* __restrict__ bo,
                 float* __restrict__ Cout)
{
    const int r = blockIdx.x, c = threadIdx.x;
    g_q[(size_t)r * 256 + c] = bq[c] * 0.0625f;
    const int idx = (((r >> 10) * Hn + (c >> 5)) * Ln + (r & 1023)) * DHn + (c & 31);
    g_k[idx] = bk[c];
    g_v[idx] = bv[c];
    Cout[(size_t)r * 256 + c] = bo[c];
}

// ---------------- tf32 helpers ------------------------------------------------
__device__ __forceinline__ uint32_t cvt_tf32(float x) {
    uint32_t r;
    asm("cvt.rna.tf32.f32 %0, %1;" : "=r"(r) : "f"(x));
    return r;
}

__device__ __forceinline__ void sts_split(uint32_t* H, uint32_t* L, int off, float4 v) {
    uint32_t h0 = cvt_tf32(v.x), h1 = cvt_tf32(v.y);
    uint32_t h2 = cvt_tf32(v.z), h3 = cvt_tf32(v.w);
    uint32_t l0 = cvt_tf32(v.x - __uint_as_float(h0));
    uint32_t l1 = cvt_tf32(v.y - __uint_as_float(h1));
    uint32_t l2 = cvt_tf32(v.z - __uint_as_float(h2));
    uint32_t l3 = cvt_tf32(v.w - __uint_as_float(h3));
    *(uint4*)(H + off) = make_uint4(h0, h1, h2, h3);
    *(uint4*)(L + off) = make_uint4(l0, l1, l2, l3);
}

__device__ __forceinline__ void mma8(float (&c)[4],
                                     uint32_t a0, uint32_t a1, uint32_t a2, uint32_t a3,
                                     uint32_t b0, uint32_t b1) {
    asm volatile(
        "mma.sync.aligned.m16n8k8.row.col.f32.tf32.tf32.f32 "
        "{%0,%1,%2,%3}, {%4,%5,%6,%7}, {%8,%9}, {%0,%1,%2,%3};"
        : "+f"(c[0]), "+f"(c[1]), "+f"(c[2]), "+f"(c[3])
        : "r"(a0), "r"(a1), "r"(a2), "r"(a3), "r"(b0), "r"(b1));
}

// ---------------- 64x64 tensor-core GEMM body (3xTF32), K half ---------------
// Identical fragment math to R14; processes K range [koff, koff+128).
__device__ __forceinline__ void mma64_body(const float* __restrict__ A,
                                           const float* __restrict__ W,
                                           int row0, int col0, int koff,
                                           float (&c)[4][4],
                                           uint32_t* Ah, uint32_t* Al,
                                           uint32_t* Bh, uint32_t* Bl)
{
    const int tid  = threadIdx.x;
    const int warp = tid >> 5, lane = tid & 31;
    const int g = lane >> 2, t = lane & 3;
    const int wr0 = (warp & 3) * 16;   // warp row within CTA tile
    const int wc0 = (warp >> 2) * 32;  // warp col within CTA tile

    const int lrow = tid >> 2;
    const int kq   = (tid & 3) * 8;

    const float* Ap = A + (size_t)(row0 + lrow) * 256 + koff + kq;
    const float* Wp = W + (size_t)(col0 + lrow) * 256 + koff + kq;

    // prefetch chunk 0
    float4 ra0 = *(const float4*)(Ap);
    float4 ra1 = *(const float4*)(Ap + 4);
    float4 rw0 = *(const float4*)(Wp);
    float4 rw1 = *(const float4*)(Wp + 4);

#pragma unroll 1
    for (int kc = 0; kc < 4; kc++) {        // 4 chunks of K=32 (half of K=256)
        __syncthreads();
        sts_split(Ah, Al, lrow * KPAD + kq,     ra0);
        sts_split(Ah, Al, lrow * KPAD + kq + 4, ra1);
        sts_split(Bh, Bl, lrow * KPAD + kq,     rw0);
        sts_split(Bh, Bl, lrow * KPAD + kq + 4, rw1);
        __syncthreads();

        if (kc < 3) {                       // issue next chunk's loads early
            ra0 = *(const float4*)(Ap + (kc + 1) * 32);
            ra1 = *(const float4*)(Ap + (kc + 1) * 32 + 4);
            rw0 = *(const float4*)(Wp + (kc + 1) * 32);
            rw1 = *(const float4*)(Wp + (kc + 1) * 32 + 4);
        }

#pragma unroll
        for (int ks = 0; ks < 4; ks++) {    // 4 k8-steps per chunk
            const int k0 = ks * 8;
            const int ar0 = (wr0 + g) * KPAD + k0 + t;
            const int ar1 = (wr0 + g + 8) * KPAD + k0 + t;
            uint32_t ah0 = Ah[ar0],     ah1 = Ah[ar1];
            uint32_t ah2 = Ah[ar0 + 4], ah3 = Ah[ar1 + 4];
            uint32_t al0 = Al[ar0],     al1 = Al[ar1];
            uint32_t al2 = Al[ar0 + 4], al3 = Al[ar1 + 4];
#pragma unroll
            for (int j = 0; j < 4; j++) {
                const int br = (wc0 + j * 8 + g) * KPAD + k0 + t;
                uint32_t bh0 = Bh[br], bh1 = Bh[br + 4];
                uint32_t bl0 = Bl[br], bl1 = Bl[br + 4];
                mma8(c[j], ah0, ah1, ah2, ah3, bh0, bh1);  // hi*hi
                mma8(c[j], ah0, ah1, ah2, ah3, bl0, bl1);  // hi*lo
                mma8(c[j], al0, al1, al2, al3, bh0, bh1);  // lo*hi
            }
        }
    }
}

// ---------------- fused QKV projection (tensor core, split-K=2) ---------------
__global__ void __launch_bounds__(256)
qkv_gemm_kernel(const float* __restrict__ A,
                const float* __restrict__ Wq,
                const float* __restrict__ Wk,
                const float* __restrict__ Wv)
{
    __shared__ __align__(16) uint32_t Ah[64 * KPAD], Al[64 * KPAD];
    __shared__ __align__(16) uint32_t Bh[64 * KPAD], Bl[64 * KPAD];

    const int wsel = blockIdx.x >> 2;            // 0=Q 1=K 2=V
    const int col0 = (blockIdx.x & 3) * 64;
    const int row0 = blockIdx.y * 64;
    const int koff = blockIdx.z * 128;

    const float* W = (wsel == 0) ? Wq : (wsel == 1) ? Wk : Wv;

    float c[4][4];
#pragma unroll
    for (int j = 0; j < 4; j++)
#pragma unroll
        for (int i = 0; i < 4; i++) c[j][i] = 0.f;

    mma64_body(A, W, row0, col0, koff, c, Ah, Al, Bh, Bl);

    const int lane = threadIdx.x & 31, warp = threadIdx.x >> 5;
    const int g = lane >> 2, t = lane & 3;
    const int wr0 = (warp & 3) * 16, wc0 = (warp >> 2) * 32;

#pragma unroll
    for (int j = 0; j < 4; j++) {
        const int cc = col0 + wc0 + j * 8 + 2 * t;
#pragma unroll
        for (int half = 0; half < 2; half++) {
            const int r = row0 + wr0 + g + half * 8;
            const float v0 = c[j][half * 2 + 0];
            const float v1 = c[j][half * 2 + 1];
            if (wsel == 0) {
                atomicAdd(&g_q[(size_t)r * 256 + cc],     v0 * 0.0625f);
                atomicAdd(&g_q[(size_t)r * 256 + cc + 1], v1 * 0.0625f);
            } else {
                int idx = (((r >> 10) * Hn + (cc >> 5)) * Ln + (r & 1023)) * DHn + (cc & 31);
                float* dst = (wsel == 1) ? g_k : g_v;
                atomicAdd(&dst[idx],     v0);
                atomicAdd(&dst[idx + 1], v1);
            }
        }
    }
}

// ---------------- output projection (tensor core, split-K=2) ------------------
__global__ void __launch_bounds__(256)
out_gemm_kernel(const float* __restrict__ A, const float* __restrict__ W,
                float* __restrict__ C)
{
    __shared__ __align__(16) uint32_t Ah[64 * KPAD], Al[64 * KPAD];
    __shared__ __align__(16) uint32_t Bh[64 * KPAD], Bl[64 * KPAD];

    const int col0 = blockIdx.x * 64;
    const int row0 = blockIdx.y * 64;
    const int koff = blockIdx.z * 128;

    float c[4][4];
#pragma unroll
    for (int j = 0; j < 4; j++)
#pragma unroll
        for (int i = 0; i < 4; i++) c[j][i] = 0.f;

    mma64_body(A, W, row0, col0, koff, c, Ah, Al, Bh, Bl);

    const int lane = threadIdx.x & 31, warp = threadIdx.x >> 5;
    const int g = lane >> 2, t = lane & 3;
    const int wr0 = (warp & 3) * 16, wc0 = (warp >> 2) * 32;

#pragma unroll
    for (int j = 0; j < 4; j++) {
        const int cc = col0 + wc0 + j * 8 + 2 * t;
#pragma unroll
        for (int half = 0; half < 2; half++) {
            const int r = row0 + wr0 + g + half * 8;
            atomicAdd(&C[(size_t)r * 256 + cc],     c[j][half * 2 + 0]);
            atomicAdd(&C[(size_t)r * 256 + cc + 1], c[j][half * 2 + 1]);
        }
    }
}

// ---------------- fused sparse attention (R14 version — known good) ----------
__global__ void __launch_bounds__(256)
attn_kernel(const void* __restrict__ AdjRaw, const float* __restrict__ Eg,
            float* __restrict__ Ob)
{
    __shared__ float q_s[En];
    __shared__ int   m_list[Ln];
    __shared__ float sc[Hn][Ln];
    __shared__ int   m_cnt;

    const int n    = blockIdx.x;
    const int b    = blockIdx.y;
    const int tid  = threadIdx.x;
    const int w    = tid >> 5;
    const int lane = tid & 31;
    const int g    = lane >> 3;
    const int sub  = lane & 7;
    const int isbyte = g_adj_is_byte;

    q_s[tid] = g_q[(size_t)(b * Ln + n) * En + tid];
    if (tid == 0) m_cnt = 0;
    __syncthreads();

    const unsigned char* arow8  = (const unsigned char*)AdjRaw + (size_t)(b * Ln + n) * Ln;
    const unsigned int*  arow32 = (const unsigned int*) AdjRaw + (size_t)(b * Ln + n) * Ln;
#pragma unroll
    for (int base = 0; base < Ln; base += 256) {
        int m = base + tid;
        bool valid = isbyte ? (arow8[m] != 0) : (arow32[m] != 0u);
        unsigned bal = __ballot_sync(0xffffffffu, valid);
        int pos = 0;
        if (lane == 0 && bal) pos = atomicAdd(&m_cnt, __popc(bal));
        pos = __shfl_sync(0xffffffffu, pos, 0);
        if (valid) m_list[pos + __popc(bal & ((1u << lane) - 1))] = m;
    }
    __syncthreads();
    const int cnt = m_cnt;

    const float* Kh   = g_k + (size_t)(b * Hn + w) * Ln * DHn;
    const float* Vh   = g_v + (size_t)(b * Hn + w) * Ln * DHn;
    const float* Erow = Eg + (size_t)(b * Ln + n) * Ln * DHn;

    const float4 q4 = *(const float4*)&q_s[w * DHn + sub * 4];

    for (int i = 0; i < cnt; i += 8) {
        const int j0 = i + g, j1 = i + 4 + g;
        const int m0 = m_list[(j0 < cnt) ? j0 : 0];
        const int m1 = m_list[(j1 < cnt) ? j1 : 0];
        const float4 k0 = *(const float4*)(Kh   + (size_t)m0 * DHn + sub * 4);
        const float4 e0 = *(const float4*)(Erow + (size_t)m0 * DHn + sub * 4);
        const float4 k1 = *(const float4*)(Kh   + (size_t)m1 * DHn + sub * 4);
        const float4 e1 = *(const float4*)(Erow + (size_t)m1 * DHn + sub * 4);
        float s0, s1;
        s0 = q4.x * (k0.x + e0.x);
        s1 = q4.x * (k1.x + e1.x);
        s0 = fmaf(q4.y, k0.y + e0.y, s0);
        s1 = fmaf(q4.y, k1.y + e1.y, s1);
        s0 = fmaf(q4.z, k0.z + e0.z, s0);
        s1 = fmaf(q4.z, k1.z + e1.z, s1);
        s0 = fmaf(q4.w, k0.w + e0.w, s0);
        s1 = fmaf(q4.w, k1.w + e1.w, s1);
        s0 += __shfl_xor_sync(0xffffffffu, s0, 1);
        s1 += __shfl_xor_sync(0xffffffffu, s1, 1);
        s0 += __shfl_xor_sync(0xffffffffu, s0, 2);
        s1 += __shfl_xor_sync(0xffffffffu, s1, 2);
        s0 += __shfl_xor_sync(0xffffffffu, s0, 4);
        s1 += __shfl_xor_sync(0xffffffffu, s1, 4);
        if (sub == 0) {
            if (j0 < cnt) sc[w][j0] = s0;
            if (j1 < cnt) sc[w][j1] = s1;
        }
    }
    __syncwarp();

    float mx = -1e30f;
    for (int j = lane; j < cnt; j += 32) mx = fmaxf(mx, sc[w][j]);
#pragma unroll
    for (int off = 16; off > 0; off >>= 1)
        mx = fmaxf(mx, __shfl_xor_sync(0xffffffffu, mx, off));

    float sum = 0.f;
    for (int j = lane; j < cnt; j += 32) {
        float p = __expf(sc[w][j] - mx);
        sc[w][j] = p;
        sum += p;
    }
#pragma unroll
    for (int off = 16; off > 0; off >>= 1)
        sum += __shfl_xor_sync(0xffffffffu, sum, off);
    const float inv = 1.f / sum;
    __syncwarp();

    float4 acc0 = make_float4(0.f, 0.f, 0.f, 0.f);
    float4 acc1 = make_float4(0.f, 0.f, 0.f, 0.f);
    for (int j = 0; j < cnt; j += 8) {
        const int j0 = j + g, j1 = j + 4 + g;
        const bool ok0 = (j0 < cnt), ok1 = (j1 < cnt);
        const int m0 = m_list[ok0 ? j0 : 0];
        const int m1 = m_list[ok1 ? j1 : 0];
        const float p0 = ok0 ? sc[w][j0] : 0.f;
        const float p1 = ok1 ? sc[w][j1] : 0.f;
        const float4 v0 = *(const float4*)(Vh + (size_t)m0 * DHn + sub * 4);
        const float4 v1 = *(const float4*)(Vh + (size_t)m1 * DHn + sub * 4);
        acc0.x = fmaf(p0, v0.x, acc0.x);
        acc0.y = fmaf(p0, v0.y, acc0.y);
        acc0.z = fmaf(p0, v0.z, acc0.z);
        acc0.w = fmaf(p0, v0.w, acc0.w);
        acc1.x = fmaf(p1, v1.x, acc1.x);
        acc1.y = fmaf(p1, v1.y, acc1.y);
        acc1.z = fmaf(p1, v1.z, acc1.z);
        acc1.w = fmaf(p1, v1.w, acc1.w);
    }
    float4 acc = make_float4(acc0.x + acc1.x, acc0.y + acc1.y,
                             acc0.z + acc1.z, acc0.w + acc1.w);
#pragma unroll
    for (int off = 8; off <= 16; off <<= 1) {
        acc.x += __shfl_xor_sync(0xffffffffu, acc.x, off);
        acc.y += __shfl_xor_sync(0xffffffffu, acc.y, off);
        acc.z += __shfl_xor_sync(0xffffffffu, acc.z, off);
        acc.w += __shfl_xor_sync(0xffffffffu, acc.w, off);
    }
    if (g == 0) {
        float4 o = make_float4(acc.x * inv, acc.y * inv, acc.z * inv, acc.w * inv);
        *(float4*)(Ob + (size_t)(b * Ln + n) * En + w * DHn + sub * 4) = o;
    }
}

// ---------------- launch ----------------------------------------------------
extern "C" void kernel_launch(void* const* d_in, const int* in_sizes, int n_in,
                              void* d_out, int out_size)
{
    const float* nf  = (const float*)d_in[0];
    const void*  adj = d_in[1];
    const float* eg  = (const float*)d_in[2];
    const float* Wq = (const float*)d_in[3];
    const float* bq = (const float*)d_in[4];
    const float* Wk = (const float*)d_in[5];
    const float* bk = (const float*)d_in[6];
    const float* Wv = (const float*)d_in[7];
    const float* bv = (const float*)d_in[8];
    const float* Wo = (const float*)d_in[9];
    const float* bo = (const float*)d_in[10];
    float* out = (float*)d_out;

    float *at;
    cudaGetSymbolAddress((void**)&at, g_attn);

    detect_adj_kernel<<<1, 1024>>>((const unsigned char*)adj);
    bias_init_kernel<<<Bn * Ln, 256>>>(bq, bk, bv, bo, out);

    dim3 qkv_grid(12, (Bn * Ln) / 64, 2);   // 1536 CTAs (split-K=2)
    qkv_gemm_kernel<<<qkv_grid, 256>>>(nf, Wq, Wk, Wv);

    dim3 agrid(Ln, Bn);                     // 4096 CTAs
    attn_kernel<<<agrid, 256>>>(adj, eg, at);

    dim3 ogrid(En / 64, (Bn * Ln) / 64, 2); // 512 CTAs (split-K=2)
    out_gemm_kernel<<<ogrid, 256>>>(at, Wo, out);
}

// round 17
// speedup vs baseline: 1.1394x; 1.0566x over previous
#include <cuda_runtime.h>
#include <cuda_bf16.h>
#include <cstddef>
#include <cstdint>

// Problem constants
#define Bn  4
#define Ln  1024
#define En  256
#define Hn  8
#define DHn 32
#define KPAD 36   // smem k-row stride (floats): conflict-free frag loads, 16B-aligned

// ---------------- scratch (device globals; no allocation allowed) -----------
__device__ float g_q[Bn * Ln * En];        // Q pre-scaled by 1/16, [b][n][h*32+d]
__device__ float g_k[Bn * Hn * Ln * DHn];  // K head-major [b][h][m][d]
__device__ float g_v[Bn * Hn * Ln * DHn];  // V head-major [b][h][m][d]
__device__ float g_attn[Bn * Ln * En];     // attention output [b][n][h*32+d]
__device__ int   g_adj_is_byte;            // 1 = adjacency stored as 1-byte elems

// ---------------- adjacency dtype detection (parallel) -----------------------
__global__ void __launch_bounds__(1024)
detect_adj_kernel(const unsigned char* __restrict__ adj)
{
    __shared__ int ok;
    if (threadIdx.x == 0) ok = 1;
    __syncthreads();
    if (adj[(size_t)threadIdx.x * Ln + threadIdx.x] != 1) ok = 0;  // benign race
    __syncthreads();
    if (threadIdx.x == 0) g_adj_is_byte = ok;
}

// ---------------- tf32 helpers ------------------------------------------------
__device__ __forceinline__ uint32_t cvt_tf32(float x) {
    uint32_t r;
    asm("cvt.rna.tf32.f32 %0, %1;" : "=r"(r) : "f"(x));
    return r;
}

__device__ __forceinline__ void sts_split(uint32_t* H, uint32_t* L, int off, float4 v) {
    uint32_t h0 = cvt_tf32(v.x), h1 = cvt_tf32(v.y);
    uint32_t h2 = cvt_tf32(v.z), h3 = cvt_tf32(v.w);
    uint32_t l0 = cvt_tf32(v.x - __uint_as_float(h0));
    uint32_t l1 = cvt_tf32(v.y - __uint_as_float(h1));
    uint32_t l2 = cvt_tf32(v.z - __uint_as_float(h2));
    uint32_t l3 = cvt_tf32(v.w - __uint_as_float(h3));
    *(uint4*)(H + off) = make_uint4(h0, h1, h2, h3);
    *(uint4*)(L + off) = make_uint4(l0, l1, l2, l3);
}

__device__ __forceinline__ void mma8(float (&c)[4],
                                     uint32_t a0, uint32_t a1, uint32_t a2, uint32_t a3,
                                     uint32_t b0, uint32_t b1) {
    asm volatile(
        "mma.sync.aligned.m16n8k8.row.col.f32.tf32.tf32.f32 "
        "{%0,%1,%2,%3}, {%4,%5,%6,%7}, {%8,%9}, {%0,%1,%2,%3};"
        : "+f"(c[0]), "+f"(c[1]), "+f"(c[2]), "+f"(c[3])
        : "r"(a0), "r"(a1), "r"(a2), "r"(a3), "r"(b0), "r"(b1));
}

// ---------------- 64x64 tensor-core GEMM body (3xTF32) — R14 version ---------
__device__ __forceinline__ void mma64_body(const float* __restrict__ A,
                                           const float* __restrict__ W,
                                           int row0, int col0,
                                           float (&c)[4][4],
                                           uint32_t* Ah, uint32_t* Al,
                                           uint32_t* Bh, uint32_t* Bl)
{
    const int tid  = threadIdx.x;
    const int warp = tid >> 5, lane = tid & 31;
    const int g = lane >> 2, t = lane & 3;
    const int wr0 = (warp & 3) * 16;
    const int wc0 = (warp >> 2) * 32;

    const int lrow = tid >> 2;
    const int kq   = (tid & 3) * 8;

    const float* Ap = A + (size_t)(row0 + lrow) * 256 + kq;
    const float* Wp = W + (size_t)(col0 + lrow) * 256 + kq;

    float4 ra0 = *(const float4*)(Ap);
    float4 ra1 = *(const float4*)(Ap + 4);
    float4 rw0 = *(const float4*)(Wp);
    float4 rw1 = *(const float4*)(Wp + 4);

#pragma unroll 1
    for (int kc = 0; kc < 8; kc++) {
        __syncthreads();
        sts_split(Ah, Al, lrow * KPAD + kq,     ra0);
        sts_split(Ah, Al, lrow * KPAD + kq + 4, ra1);
        sts_split(Bh, Bl, lrow * KPAD + kq,     rw0);
        sts_split(Bh, Bl, lrow * KPAD + kq + 4, rw1);
        __syncthreads();

        if (kc < 7) {
            ra0 = *(const float4*)(Ap + (kc + 1) * 32);
            ra1 = *(const float4*)(Ap + (kc + 1) * 32 + 4);
            rw0 = *(const float4*)(Wp + (kc + 1) * 32);
            rw1 = *(const float4*)(Wp + (kc + 1) * 32 + 4);
        }

#pragma unroll
        for (int ks = 0; ks < 4; ks++) {
            const int k0 = ks * 8;
            const int ar0 = (wr0 + g) * KPAD + k0 + t;
            const int ar1 = (wr0 + g + 8) * KPAD + k0 + t;
            uint32_t ah0 = Ah[ar0],     ah1 = Ah[ar1];
            uint32_t ah2 = Ah[ar0 + 4], ah3 = Ah[ar1 + 4];
            uint32_t al0 = Al[ar0],     al1 = Al[ar1];
            uint32_t al2 = Al[ar0 + 4], al3 = Al[ar1 + 4];
#pragma unroll
            for (int j = 0; j < 4; j++) {
                const int br = (wc0 + j * 8 + g) * KPAD + k0 + t;
                uint32_t bh0 = Bh[br], bh1 = Bh[br + 4];
                uint32_t bl0 = Bl[br], bl1 = Bl[br + 4];
                mma8(c[j], ah0, ah1, ah2, ah3, bh0, bh1);  // hi*hi
                mma8(c[j], ah0, ah1, ah2, ah3, bl0, bl1);  // hi*lo
                mma8(c[j], al0, al1, al2, al3, bh0, bh1);  // lo*hi
            }
        }
    }
}

// ---------------- fused QKV projection (tensor core) — R14 version ------------
__global__ void __launch_bounds__(256)
qkv_gemm_kernel(const float* __restrict__ A,
                const float* __restrict__ Wq, const float* __restrict__ bq,
                const float* __restrict__ Wk, const float* __restrict__ bk,
                const float* __restrict__ Wv, const float* __restrict__ bv)
{
    __shared__ __align__(16) uint32_t Ah[64 * KPAD], Al[64 * KPAD];
    __shared__ __align__(16) uint32_t Bh[64 * KPAD], Bl[64 * KPAD];

    const int wsel = blockIdx.x >> 2;            // 0=Q 1=K 2=V
    const int col0 = (blockIdx.x & 3) * 64;
    const int row0 = blockIdx.y * 64;

    const float* W    = (wsel == 0) ? Wq : (wsel == 1) ? Wk : Wv;
    const float* bias = (wsel == 0) ? bq : (wsel == 1) ? bk : bv;

    float c[4][4];
#pragma unroll
    for (int j = 0; j < 4; j++)
#pragma unroll
        for (int i = 0; i < 4; i++) c[j][i] = 0.f;

    mma64_body(A, W, row0, col0, c, Ah, Al, Bh, Bl);

    const int lane = threadIdx.x & 31, warp = threadIdx.x >> 5;
    const int g = lane >> 2, t = lane & 3;
    const int wr0 = (warp & 3) * 16, wc0 = (warp >> 2) * 32;

#pragma unroll
    for (int j = 0; j < 4; j++) {
        const int cc = col0 + wc0 + j * 8 + 2 * t;
        const float b0 = bias[cc], b1 = bias[cc + 1];
#pragma unroll
        for (int half = 0; half < 2; half++) {
            const int r = row0 + wr0 + g + half * 8;
            float v0 = c[j][half * 2 + 0] + b0;
            float v1 = c[j][half * 2 + 1] + b1;
            if (wsel == 0) {
                *(float2*)&g_q[(size_t)r * 256 + cc] =
                    make_float2(v0 * 0.0625f, v1 * 0.0625f);
            } else {
                int idx = (((r >> 10) * Hn + (cc >> 5)) * Ln + (r & 1023)) * DHn + (cc & 31);
                float* dst = (wsel == 1) ? g_k : g_v;
                *(float2*)&dst[idx] = make_float2(v0, v1);
            }
        }
    }
}

// ---------------- output projection (tensor core) — R14 version ---------------
__global__ void __launch_bounds__(256)
out_gemm_kernel(const float* __restrict__ A, const float* __restrict__ W,
                const float* __restrict__ bias, float* __restrict__ C)
{
    __shared__ __align__(16) uint32_t Ah[64 * KPAD], Al[64 * KPAD];
    __shared__ __align__(16) uint32_t Bh[64 * KPAD], Bl[64 * KPAD];

    const int col0 = blockIdx.x * 64;
    const int row0 = blockIdx.y * 64;

    float c[4][4];
#pragma unroll
    for (int j = 0; j < 4; j++)
#pragma unroll
        for (int i = 0; i < 4; i++) c[j][i] = 0.f;

    mma64_body(A, W, row0, col0, c, Ah, Al, Bh, Bl);

    const int lane = threadIdx.x & 31, warp = threadIdx.x >> 5;
    const int g = lane >> 2, t = lane & 3;
    const int wr0 = (warp & 3) * 16, wc0 = (warp >> 2) * 32;

#pragma unroll
    for (int j = 0; j < 4; j++) {
        const int cc = col0 + wc0 + j * 8 + 2 * t;
        const float b0 = bias[cc], b1 = bias[cc + 1];
#pragma unroll
        for (int half = 0; half < 2; half++) {
            const int r = row0 + wr0 + g + half * 8;
            *(float2*)&C[(size_t)r * 256 + cc] =
                make_float2(c[j][half * 2 + 0] + b0, c[j][half * 2 + 1] + b1);
        }
    }
}

// ---------------- fused sparse attention: flash-style single pass ------------
// CTA = (b, n). 8 warps = 8 heads. Per 8 neighbors: K,E,V loaded together
// (6 LDG.128 in flight), online softmax (running max/sum, rescaled V acc).
// No score array -> smem 5 KB, one pass over the neighbor list.
__global__ void __launch_bounds__(256)
attn_kernel(const void* __restrict__ AdjRaw, const float* __restrict__ Eg,
            float* __restrict__ Ob)
{
    __shared__ float q_s[En];
    __shared__ int   m_list[Ln];
    __shared__ int   m_cnt;

    const int n    = blockIdx.x;
    const int b    = blockIdx.y;
    const int tid  = threadIdx.x;
    const int w    = tid >> 5;       // head
    const int lane = tid & 31;
    const int g    = lane >> 3;      // neighbor sub-group 0..3
    const int sub  = lane & 7;       // d-quad index (d = sub*4..sub*4+3)
    const int isbyte = g_adj_is_byte;

    q_s[tid] = g_q[(size_t)(b * Ln + n) * En + tid];
    if (tid == 0) m_cnt = 0;
    __syncthreads();

    // ---- compact the adjacency row into m_list ----
    const unsigned char* arow8  = (const unsigned char*)AdjRaw + (size_t)(b * Ln + n) * Ln;
    const unsigned int*  arow32 = (const unsigned int*) AdjRaw + (size_t)(b * Ln + n) * Ln;
#pragma unroll
    for (int base = 0; base < Ln; base += 256) {
        int m = base + tid;
        bool valid = isbyte ? (arow8[m] != 0) : (arow32[m] != 0u);
        unsigned bal = __ballot_sync(0xffffffffu, valid);
        int pos = 0;
        if (lane == 0 && bal) pos = atomicAdd(&m_cnt, __popc(bal));
        pos = __shfl_sync(0xffffffffu, pos, 0);
        if (valid) m_list[pos + __popc(bal & ((1u << lane) - 1))] = m;
    }
    __syncthreads();
    const int cnt = m_cnt;   // >= 1 (diagonal always set)

    const float* Kh   = g_k + (size_t)(b * Hn + w) * Ln * DHn;
    const float* Vh   = g_v + (size_t)(b * Hn + w) * Ln * DHn;
    const float* Erow = Eg + (size_t)(b * Ln + n) * Ln * DHn;

    const float4 q4 = *(const float4*)&q_s[w * DHn + sub * 4];

    float4 acc0 = make_float4(0.f, 0.f, 0.f, 0.f);
    float4 acc1 = make_float4(0.f, 0.f, 0.f, 0.f);
    float m_run = -1e30f;
    float s_run = 0.f;

    for (int j = 0; j < cnt; j += 8) {
        const int j0 = j + g, j1 = j + 4 + g;
        const bool ok0 = (j0 < cnt), ok1 = (j1 < cnt);
        const int m0 = m_list[ok0 ? j0 : 0];
        const int m1 = m_list[ok1 ? j1 : 0];
        // 6 independent LDG.128 in flight
        const float4 k0 = *(const float4*)(Kh   + (size_t)m0 * DHn + sub * 4);
        const float4 e0 = *(const float4*)(Erow + (size_t)m0 * DHn + sub * 4);
        const float4 v0 = *(const float4*)(Vh   + (size_t)m0 * DHn + sub * 4);
        const float4 k1 = *(const float4*)(Kh   + (size_t)m1 * DHn + sub * 4);
        const float4 e1 = *(const float4*)(Erow + (size_t)m1 * DHn + sub * 4);
        const float4 v1 = *(const float4*)(Vh   + (size_t)m1 * DHn + sub * 4);

        float s0, s1;
        s0 = q4.x * (k0.x + e0.x);
        s1 = q4.x * (k1.x + e1.x);
        s0 = fmaf(q4.y, k0.y + e0.y, s0);
        s1 = fmaf(q4.y, k1.y + e1.y, s1);
        s0 = fmaf(q4.z, k0.z + e0.z, s0);
        s1 = fmaf(q4.z, k1.z + e1.z, s1);
        s0 = fmaf(q4.w, k0.w + e0.w, s0);
        s1 = fmaf(q4.w, k1.w + e1.w, s1);
        s0 += __shfl_xor_sync(0xffffffffu, s0, 1);
        s1 += __shfl_xor_sync(0xffffffffu, s1, 1);
        s0 += __shfl_xor_sync(0xffffffffu, s0, 2);
        s1 += __shfl_xor_sync(0xffffffffu, s1, 2);
        s0 += __shfl_xor_sync(0xffffffffu, s0, 4);
        s1 += __shfl_xor_sync(0xffffffffu, s1, 4);
        if (!ok0) s0 = -1e30f;   // padded slot -> p = 0
        if (!ok1) s1 = -1e30f;

        // warp-wide chunk max (groups differ in lane bits 3,4)
        float mc = fmaxf(s0, s1);
        mc = fmaxf(mc, __shfl_xor_sync(0xffffffffu, mc, 8));
        mc = fmaxf(mc, __shfl_xor_sync(0xffffffffu, mc, 16));
        const float m_new = fmaxf(m_run, mc);   // finite: chunk has >=1 valid

        const float f  = __expf(m_run - m_new); // first iter: exp(-huge) = 0
        const float p0 = __expf(s0 - m_new);
        const float p1 = __expf(s1 - m_new);
        float ps = p0 + p1;
        ps += __shfl_xor_sync(0xffffffffu, ps, 8);
        ps += __shfl_xor_sync(0xffffffffu, ps, 16);
        s_run = s_run * f + ps;
        m_run = m_new;

        acc0.x = fmaf(p0, v0.x, acc0.x * f);
        acc0.y = fmaf(p0, v0.y, acc0.y * f);
        acc0.z = fmaf(p0, v0.z, acc0.z * f);
        acc0.w = fmaf(p0, v0.w, acc0.w * f);
        acc1.x = fmaf(p1, v1.x, acc1.x * f);
        acc1.y = fmaf(p1, v1.y, acc1.y * f);
        acc1.z = fmaf(p1, v1.z, acc1.z * f);
        acc1.w = fmaf(p1, v1.w, acc1.w * f);
    }

    float4 acc = make_float4(acc0.x + acc1.x, acc0.y + acc1.y,
                             acc0.z + acc1.z, acc0.w + acc1.w);
    // combine the 4 neighbor-groups (all scaled by the same m_run)
#pragma unroll
    for (int off = 8; off <= 16; off <<= 1) {
        acc.x += __shfl_xor_sync(0xffffffffu, acc.x, off);
        acc.y += __shfl_xor_sync(0xffffffffu, acc.y, off);
        acc.z += __shfl_xor_sync(0xffffffffu, acc.z, off);
        acc.w += __shfl_xor_sync(0xffffffffu, acc.w, off);
    }
    if (g == 0) {
        const float inv = 1.f / s_run;
        float4 o = make_float4(acc.x * inv, acc.y * inv, acc.z * inv, acc.w * inv);
        *(float4*)(Ob + (size_t)(b * Ln + n) * En + w * DHn + sub * 4) = o;
    }
}

// ---------------- launch ----------------------------------------------------
extern "C" void kernel_launch(void* const* d_in, const int* in_sizes, int n_in,
                              void* d_out, int out_size)
{
    const float* nf  = (const float*)d_in[0];
    const void*  adj = d_in[1];
    const float* eg  = (const float*)d_in[2];
    const float* Wq = (const float*)d_in[3];
    const float* bq = (const float*)d_in[4];
    const float* Wk = (const float*)d_in[5];
    const float* bk = (const float*)d_in[6];
    const float* Wv = (const float*)d_in[7];
    const float* bv = (const float*)d_in[8];
    const float* Wo = (const float*)d_in[9];
    const float* bo = (const float*)d_in[10];
    float* out = (float*)d_out;

    float *at;
    cudaGetSymbolAddress((void**)&at, g_attn);

    detect_adj_kernel<<<1, 1024>>>((const unsigned char*)adj);

    dim3 qkv_grid(12, (Bn * Ln) / 64);   // 768 CTAs
    qkv_gemm_kernel<<<qkv_grid, 256>>>(nf, Wq, bq, Wk, bk, Wv, bv);

    dim3 agrid(Ln, Bn);                  // 4096 CTAs
    attn_kernel<<<agrid, 256>>>(adj, eg, at);

    dim3 ogrid(En / 64, (Bn * Ln) / 64); // 256 CTAs
    out_gemm_kernel<<<ogrid, 256>>>(at, Wo, bo, out);
}